// round 5
// baseline (speedup 1.0000x reference)
#include <cuda_runtime.h>
#include <cstdint>

// PatchesCreate: [64, 384, 384, 3] f32 -> [64, 576, 768] f32
//
// Tile = (b, gy): 16 full image rows = 73728B contiguous in input, mapping
// exactly onto 24 consecutive patches = 73728B contiguous in output.
// Both GMEM streams perfectly sequential; permutation done on the SMEM
// read side (conflict-free: each 8-lane crossbar phase reads a contiguous
// 128B smem region).
//
// cp.async.cg (LDGSTS.128) global->shared: no register staging, no L1
// pollution. 512 thr x 9 float4. 3 CTAs/SM (216KB smem) overlap phases.

static constexpr int TPB        = 512;
static constexpr int TILE4      = 16 * 288;     // 4608 float4 = 72KB
static constexpr int LOADS      = TILE4 / TPB;  // 9
static constexpr int SMEM_BYTES = TILE4 * 16;   // 73728

__global__ void __launch_bounds__(TPB, 3)
patches_kernel(const float4* __restrict__ in, float4* __restrict__ out)
{
    extern __shared__ float4 sm[];

    int b  = blockIdx.x / 24;
    int gy = blockIdx.x - b * 24;

    const float4* __restrict__ src = in  + (b * 384 + gy * 16) * 288;
    float4*       __restrict__ dst = out + (b * 576 + gy * 24) * 192;

    uint32_t sbase;
    asm("{ .reg .u64 t; cvta.to.shared.u64 t, %1; cvt.u32.u64 %0, t; }"
        : "=r"(sbase) : "l"(sm));

    // Phase 1: sequential global -> shared, bypassing registers and L1.
#pragma unroll
    for (int j = 0; j < LOADS; ++j) {
        int idx = threadIdx.x + j * TPB;
        uint32_t      daddr = sbase + idx * 16;
        const float4* gaddr = src + idx;
        asm volatile("cp.async.cg.shared.global [%0], [%1], 16;"
                     :: "r"(daddr), "l"(gaddr) : "memory");
    }
    asm volatile("cp.async.commit_group;" ::: "memory");
    asm volatile("cp.async.wait_group 0;" ::: "memory");
    __syncthreads();

    // Phase 2: permuted SMEM read, sequential streaming write.
    // out-local o -> (gx = o/192, py = (o%192)/12, lane = o%12)
    // in-local     = py*288 + gx*12 + lane
#pragma unroll
    for (int j = 0; j < LOADS; ++j) {
        int o    = threadIdx.x + j * TPB;
        int gx   = o / 192;
        int r    = o - gx * 192;
        int py   = r / 12;
        int lane = r - py * 12;
        float4 v = sm[py * 288 + gx * 12 + lane];
        __stcs(&dst[o], v);
    }
}

extern "C" void kernel_launch(void* const* d_in, const int* in_sizes, int n_in,
                              void* d_out, int out_size)
{
    (void)in_sizes; (void)n_in; (void)out_size;
    const float4* in  = (const float4*)d_in[0];
    float4*       out = (float4*)d_out;

    cudaFuncSetAttribute(patches_kernel,
                         cudaFuncAttributeMaxDynamicSharedMemorySize,
                         SMEM_BYTES);
    patches_kernel<<<64 * 24, TPB, SMEM_BYTES>>>(in, out);
}